// round 1
// baseline (speedup 1.0000x reference)
#include <cuda_runtime.h>
#include <math.h>

#define D   256
#define G3  768
#define MAXR 4096

// ---------------- device scratch (static globals; no allocation) ----------------
__device__ float g_sub[D];
__device__ float g_gi0[G3];
__device__ float g_gh0[G3];
__device__ float g_r0[D];
__device__ float g_gi[G3];                 // gi for the broadcast r0 input
__device__ float g_gh[(size_t)MAXR * G3];  // gh_table per relation (no bias)
__device__ float g_rj[(size_t)MAXR * D];
__device__ float g_obj[(size_t)MAXR * D];

// ---------------- GEMV: out[j] = act(W[j,:] . x + b[j]) ; 8 rows/block ----------
__global__ void gemv256(const float* __restrict__ W, const float* __restrict__ x,
                        const float* __restrict__ b, float* __restrict__ out,
                        int rows, int do_tanh,
                        float* __restrict__ out2, const int* __restrict__ seed_ptr) {
    int w = threadIdx.x >> 5, l = threadIdx.x & 31;
    int j = blockIdx.x * 8 + w;
    if (j >= rows) return;
    const float* Wr = W + (size_t)j * D;
    float acc = 0.f;
#pragma unroll
    for (int i = 0; i < D / 32; i++) acc += Wr[l + i * 32] * __ldg(&x[l + i * 32]);
#pragma unroll
    for (int o = 16; o; o >>= 1) acc += __shfl_xor_sync(0xffffffffu, acc, o);
    if (l == 0) {
        acc += b[j];
        if (do_tanh) acc = tanhf(acc);
        out[j] = acc;
        if (out2) out2[(size_t)seed_ptr[0] * D + j] = acc;  // seed row = sub
    }
}

// ---------------- seed GRU combine: r0 from gi0/gh0/sub -------------------------
__global__ void gru_seed_kernel() {
    int d = threadIdx.x;
    float r = 1.f / (1.f + expf(-(g_gi0[d] + g_gh0[d])));
    float z = 1.f / (1.f + expf(-(g_gi0[D + d] + g_gh0[D + d])));
    float n = tanhf(g_gi0[2 * D + d] + r * g_gh0[2 * D + d]);
    g_r0[d] = (1.f - z) * n + z * g_sub[d];
}

// ---------------- fp32 NT GEMM: C[m,n] = act(sum_k A[m,k]*B[n,k] + bias[n]) -----
// BM=64, BK=32, 256 threads, micro-tile TM=4 x TN. N, K multiples of tiles; M ragged.
template <int BN, int TN, bool TANH>
__global__ __launch_bounds__(256) void gemm_nt(
        const float* __restrict__ A, const float* __restrict__ B,
        const float* __restrict__ bias, float* __restrict__ C,
        int M, int N, int K) {
    const int BM = 64, BK = 32, TM = 4;
    __shared__ float As[BK][BM + 4];
    __shared__ float Bs[BK][BN + 4];
    int tid = threadIdx.x;
    int m0 = blockIdx.x * BM;
    int n0 = blockIdx.y * BN;
    float acc[TM][TN];
#pragma unroll
    for (int i = 0; i < TM; i++)
#pragma unroll
        for (int j = 0; j < TN; j++) acc[i][j] = 0.f;
    int tm = (tid & 15) * TM;
    int tn = (tid >> 4) * TN;

    for (int k0 = 0; k0 < K; k0 += BK) {
#pragma unroll
        for (int i = 0; i < (BM * BK) / (256 * 4); i++) {
            int idx = tid + i * 256;
            int row = idx >> 3;  // BK/4 = 8 float4 per row
            int c4 = idx & 7;
            float4 v = make_float4(0.f, 0.f, 0.f, 0.f);
            if (m0 + row < M) v = *(const float4*)&A[(size_t)(m0 + row) * K + k0 + c4 * 4];
            As[c4 * 4 + 0][row] = v.x; As[c4 * 4 + 1][row] = v.y;
            As[c4 * 4 + 2][row] = v.z; As[c4 * 4 + 3][row] = v.w;
        }
#pragma unroll
        for (int i = 0; i < (BN * BK) / (256 * 4); i++) {
            int idx = tid + i * 256;
            int row = idx >> 3;
            int c4 = idx & 7;
            float4 v = *(const float4*)&B[(size_t)(n0 + row) * K + k0 + c4 * 4];
            Bs[c4 * 4 + 0][row] = v.x; Bs[c4 * 4 + 1][row] = v.y;
            Bs[c4 * 4 + 2][row] = v.z; Bs[c4 * 4 + 3][row] = v.w;
        }
        __syncthreads();
#pragma unroll
        for (int k = 0; k < BK; k++) {
            float4 av = *(const float4*)&As[k][tm];
            float a[TM] = {av.x, av.y, av.z, av.w};
            float bb[TN];
#pragma unroll
            for (int j4 = 0; j4 < TN / 4; j4++) {
                float4 bv = *(const float4*)&Bs[k][tn + j4 * 4];
                bb[j4 * 4 + 0] = bv.x; bb[j4 * 4 + 1] = bv.y;
                bb[j4 * 4 + 2] = bv.z; bb[j4 * 4 + 3] = bv.w;
            }
#pragma unroll
            for (int i = 0; i < TM; i++)
#pragma unroll
                for (int j = 0; j < TN; j++) acc[i][j] += a[i] * bb[j];
        }
        __syncthreads();
    }
#pragma unroll
    for (int i = 0; i < TM; i++) {
        int m = m0 + tm + i;
        if (m < M) {
#pragma unroll
            for (int j = 0; j < TN; j++) {
                float v = acc[i][j];
                if (bias) v += bias[n0 + tn + j];
                if (TANH) v = tanhf(v);
                C[(size_t)m * N + n0 + tn + j] = v;
            }
        }
    }
}

// ---------------- per-relation GRU combine: rj_table ----------------------------
__global__ void rj_kernel(const float* __restrict__ rel_table,
                          const float* __restrict__ b_hh, int R) {
    int r = blockIdx.x, d = threadIdx.x;
    const float* gh = g_gh + (size_t)r * G3;
    float hr = gh[d] + b_hh[d];
    float hz = gh[D + d] + b_hh[D + d];
    float hn = gh[2 * D + d] + b_hh[2 * D + d];
    float rr = 1.f / (1.f + expf(-(g_gi[d] + hr)));
    float z  = 1.f / (1.f + expf(-(g_gi[D + d] + hz)));
    float n  = tanhf(g_gi[2 * D + d] + rr * hn);
    g_rj[(size_t)r * D + d] = (1.f - z) * n + z * rel_table[(size_t)r * D + d];
}

// ---------------- scatter: out[tail] = state ? ent[origin] : obj[rel] -----------
__global__ void scatter_kernel(const int* __restrict__ rel_ids,
                               const int* __restrict__ tail_ids,
                               const int* __restrict__ state,
                               const int* __restrict__ origin,
                               const float* __restrict__ ent_table,
                               float* __restrict__ out, int E) {
    __shared__ int s_rel[4], s_tail[4], s_st[4], s_or[4];
    int tid = threadIdx.x;
    int e_base = blockIdx.x * 4;
    if (tid < 16) {
        int g = tid >> 2, f = tid & 3;
        int e = e_base + g;
        if (e < E) {
            if (f == 0)      s_st[g]   = state[e];
            else if (f == 1) s_rel[g]  = rel_ids[e];
            else if (f == 2) s_tail[g] = tail_ids[e];
            else             s_or[g]   = origin[e];
        }
    }
    __syncthreads();
    int g = tid >> 6, lane = tid & 63;
    int e = e_base + g;
    if (e >= E) return;
    float4* dst = (float4*)(out + (size_t)s_tail[g] * D);
    float4 v;
    if (s_st[g] == 1) {
        const float4* src = (const float4*)(ent_table + (size_t)s_or[g] * D);
        v = __ldcs(src + lane);         // random gather, no reuse
    } else {
        const float4* src = (const float4*)(g_obj + (size_t)s_rel[g] * D);
        v = __ldg(src + lane);          // 1 MB table, L2 resident
    }
    __stcs(dst + lane, v);              // streaming store: written once
}

// --------------------------------- launcher -------------------------------------
extern "C" void kernel_launch(void* const* d_in, const int* in_sizes, int n_in,
                              void* d_out, int out_size) {
    const float* encoder = (const float*)d_in[0];
    const float* mask    = (const float*)d_in[1];
    const float* entT    = (const float*)d_in[2];
    const float* relT    = (const float*)d_in[3];
    const float* W_ih    = (const float*)d_in[4];
    const float* W_hh    = (const float*)d_in[5];
    const float* b_ih    = (const float*)d_in[6];
    const float* b_hh    = (const float*)d_in[7];
    const float* sub_W   = (const float*)d_in[8];
    const float* sub_b   = (const float*)d_in[9];
    const float* obj_W   = (const float*)d_in[10];
    const float* obj_b   = (const float*)d_in[11];
    const int*   rel_ids = (const int*)d_in[12];
    const int*   tail_ids= (const int*)d_in[13];
    const int*   state   = (const int*)d_in[14];
    const int*   origin  = (const int*)d_in[15];
    const int*   seed_p  = (const int*)d_in[16];
    float* out = (float*)d_out;

    int E = in_sizes[12];
    int R = in_sizes[3] / D;
    if (R > MAXR) R = MAXR;

    float *p_sub, *p_gi0, *p_gh0, *p_r0, *p_gi, *p_gh, *p_rj, *p_obj;
    cudaGetSymbolAddress((void**)&p_sub, g_sub);
    cudaGetSymbolAddress((void**)&p_gi0, g_gi0);
    cudaGetSymbolAddress((void**)&p_gh0, g_gh0);
    cudaGetSymbolAddress((void**)&p_r0,  g_r0);
    cudaGetSymbolAddress((void**)&p_gi,  g_gi);
    cudaGetSymbolAddress((void**)&p_gh,  g_gh);
    cudaGetSymbolAddress((void**)&p_rj,  g_rj);
    cudaGetSymbolAddress((void**)&p_obj, g_obj);

    // sub = tanh(sub_W @ mask + sub_b); also writes out[seed] = sub
    gemv256<<<32, 256>>>(sub_W, mask, sub_b, p_sub, 256, 1, out, seed_p);
    // gi0 = W_ih @ encoder + b_ih
    gemv256<<<96, 256>>>(W_ih, encoder, b_ih, p_gi0, 768, 0, nullptr, nullptr);
    // gh_table = rel_table @ W_hh^T  (bias added later, in rj_kernel)
    gemm_nt<128, 8, false><<<dim3((R + 63) / 64, G3 / 128), 256>>>(
        relT, W_hh, nullptr, p_gh, R, G3, D);
    // gh0 = W_hh @ sub + b_hh
    gemv256<<<96, 256>>>(W_hh, p_sub, b_hh, p_gh0, 768, 0, nullptr, nullptr);
    // r0 = GRU(encoder, sub)
    gru_seed_kernel<<<1, 256>>>();
    // gi = W_ih @ r0 + b_ih  (shared by ALL edges)
    gemv256<<<96, 256>>>(W_ih, p_r0, b_ih, p_gi, 768, 0, nullptr, nullptr);
    // rj_table per relation
    rj_kernel<<<R, 256>>>(relT, b_hh, R);
    // obj_table = tanh(rj_table @ obj_W^T + obj_b)
    gemm_nt<64, 4, true><<<dim3((R + 63) / 64, D / 64), 256>>>(
        p_rj, obj_W, obj_b, p_obj, R, D, D);
    // final scatter over edges
    scatter_kernel<<<(E + 3) / 4, 256>>>(rel_ids, tail_ids, state, origin, entT, out, E);
}

// round 3
// speedup vs baseline: 1.1044x; 1.1044x over previous
#include <cuda_runtime.h>
#include <math.h>

#define D   256
#define G3  768
#define MAXR 4096

// ---------------- device scratch (static globals; no allocation) ----------------
__device__ float g_sub[D];
__device__ float g_gi0[G3];
__device__ float g_gh0[G3];
__device__ float g_gi[G3];                 // gi for broadcast r0 input
__device__ float g_gh[(size_t)MAXR * G3];  // gh_table per relation (no bias)
__device__ float g_rj[(size_t)MAXR * D];
__device__ float g_obj[(size_t)MAXR * D];

__device__ __forceinline__ float dot8(float4 a0, float4 a1, float4 x0, float4 x1) {
    return a0.x*x0.x + a0.y*x0.y + a0.z*x0.z + a0.w*x0.w
         + a1.x*x1.x + a1.y*x1.y + a1.z*x1.z + a1.w*x1.w;
}
__device__ __forceinline__ float wred(float v) {
#pragma unroll
    for (int o = 16; o; o >>= 1) v += __shfl_xor_sync(0xffffffffu, v, o);
    return v;
}
__device__ __forceinline__ float sigf(float x) { return 1.f / (1.f + __expf(-x)); }

// ---------------- K1: sub = tanh(sub_W@mask+sub_b) (+seed write) ; gi0 ----------
__global__ void k1_sub_gi0(const float* __restrict__ sub_W, const float* __restrict__ W_ih,
                           const float* __restrict__ mask,  const float* __restrict__ enc,
                           const float* __restrict__ sub_b, const float* __restrict__ b_ih,
                           float* __restrict__ out, const int* __restrict__ seed_p) {
    int w = threadIdx.x >> 5, l = threadIdx.x & 31;
    int j = blockIdx.x * 8 + w;               // 0..1023
    const float4 *Wr, *x; float bias;
    if (j < 256) { Wr = (const float4*)(sub_W + (size_t)j * D); x = (const float4*)mask; bias = sub_b[j]; }
    else         { Wr = (const float4*)(W_ih + (size_t)(j - 256) * D); x = (const float4*)enc; bias = b_ih[j - 256]; }
    float acc = wred(dot8(Wr[l], Wr[l + 32], __ldg(x + l), __ldg(x + l + 32)));
    if (l == 0) {
        acc += bias;
        if (j < 256) { float t = tanhf(acc); g_sub[j] = t; out[(size_t)seed_p[0] * D + j] = t; }
        else g_gi0[j - 256] = acc;
    }
}

// ---------------- K2: gh0 = W_hh @ sub + b_hh -----------------------------------
__global__ void k2_gh0(const float* __restrict__ W_hh, const float* __restrict__ b_hh) {
    int w = threadIdx.x >> 5, l = threadIdx.x & 31;
    int j = blockIdx.x * 8 + w;
    const float4* Wr = (const float4*)(W_hh + (size_t)j * D);
    const float4* x  = (const float4*)g_sub;
    float acc = wred(dot8(Wr[l], Wr[l + 32], x[l], x[l + 32]));
    if (l == 0) g_gh0[j] = acc + b_hh[j];
}

// ---------------- K3: r0 (in-block) then gi = W_ih @ r0 + b_ih ------------------
__global__ void k3_gi(const float* __restrict__ W_ih, const float* __restrict__ b_ih) {
    __shared__ float r0[D];
    int t = threadIdx.x;
    {
        float r = sigf(g_gi0[t] + g_gh0[t]);
        float z = sigf(g_gi0[D + t] + g_gh0[D + t]);
        float n = tanhf(g_gi0[2 * D + t] + r * g_gh0[2 * D + t]);
        r0[t] = (1.f - z) * n + z * g_sub[t];
    }
    __syncthreads();
    int w = t >> 5, l = t & 31;
    int j = blockIdx.x * 8 + w;
    const float4* Wr = (const float4*)(W_ih + (size_t)j * D);
    const float4* x  = (const float4*)r0;
    float acc = wred(dot8(Wr[l], Wr[l + 32], x[l], x[l + 32]));
    if (l == 0) g_gi[j] = acc + b_ih[j];
}

// ---------------- fp32 NT GEMM: C[m,n] = act(A[m,:].B[n,:] + bias[n]) -----------
template <int BN, int TN, bool TANH>
__global__ __launch_bounds__(256) void gemm_nt(
        const float* __restrict__ A, const float* __restrict__ B,
        const float* __restrict__ bias, float* __restrict__ C,
        int M, int N, int K) {
    const int BM = 64, BK = 32, TM = 4;
    __shared__ float As[BK][BM + 4];
    __shared__ float Bs[BK][BN + 4];
    int tid = threadIdx.x;
    int m0 = blockIdx.x * BM;
    int n0 = blockIdx.y * BN;
    float acc[TM][TN];
#pragma unroll
    for (int i = 0; i < TM; i++)
#pragma unroll
        for (int j = 0; j < TN; j++) acc[i][j] = 0.f;
    int tm = (tid & 15) * TM;
    int tn = (tid >> 4) * TN;

    for (int k0 = 0; k0 < K; k0 += BK) {
#pragma unroll
        for (int i = 0; i < (BM * BK) / (256 * 4); i++) {
            int idx = tid + i * 256;
            int row = idx >> 3, c4 = idx & 7;
            float4 v = make_float4(0.f, 0.f, 0.f, 0.f);
            if (m0 + row < M) v = *(const float4*)&A[(size_t)(m0 + row) * K + k0 + c4 * 4];
            As[c4 * 4 + 0][row] = v.x; As[c4 * 4 + 1][row] = v.y;
            As[c4 * 4 + 2][row] = v.z; As[c4 * 4 + 3][row] = v.w;
        }
#pragma unroll
        for (int i = 0; i < (BN * BK) / (256 * 4); i++) {
            int idx = tid + i * 256;
            int row = idx >> 3, c4 = idx & 7;
            float4 v = *(const float4*)&B[(size_t)(n0 + row) * K + k0 + c4 * 4];
            Bs[c4 * 4 + 0][row] = v.x; Bs[c4 * 4 + 1][row] = v.y;
            Bs[c4 * 4 + 2][row] = v.z; Bs[c4 * 4 + 3][row] = v.w;
        }
        __syncthreads();
#pragma unroll
        for (int k = 0; k < BK; k++) {
            float4 av = *(const float4*)&As[k][tm];
            float a[TM] = {av.x, av.y, av.z, av.w};
            float bb[TN];
#pragma unroll
            for (int j4 = 0; j4 < TN / 4; j4++) {
                float4 bv = *(const float4*)&Bs[k][tn + j4 * 4];
                bb[j4 * 4 + 0] = bv.x; bb[j4 * 4 + 1] = bv.y;
                bb[j4 * 4 + 2] = bv.z; bb[j4 * 4 + 3] = bv.w;
            }
#pragma unroll
            for (int i = 0; i < TM; i++)
#pragma unroll
                for (int j = 0; j < TN; j++) acc[i][j] += a[i] * bb[j];
        }
        __syncthreads();
    }
#pragma unroll
    for (int i = 0; i < TM; i++) {
        int m = m0 + tm + i;
        if (m < M) {
#pragma unroll
            for (int j = 0; j < TN; j++) {
                float v = acc[i][j];
                if (bias) v += bias[n0 + tn + j];
                if (TANH) v = tanhf(v);
                C[(size_t)m * N + n0 + tn + j] = v;
            }
        }
    }
}

// ---------------- per-relation GRU combine: rj_table ----------------------------
__global__ void rj_kernel(const float* __restrict__ rel_table,
                          const float* __restrict__ b_hh, int R) {
    int r = blockIdx.x, d = threadIdx.x;
    const float* gh = g_gh + (size_t)r * G3;
    float hr = gh[d] + b_hh[d];
    float hz = gh[D + d] + b_hh[D + d];
    float hn = gh[2 * D + d] + b_hh[2 * D + d];
    float rr = sigf(g_gi[d] + hr);
    float z  = sigf(g_gi[D + d] + hz);
    float n  = tanhf(g_gi[2 * D + d] + rr * hn);
    g_rj[(size_t)r * D + d] = (1.f - z) * n + z * rel_table[(size_t)r * D + d];
}

// ---------------- scatter A: state==1 edges: out[tail] = ent[origin] ------------
// Persistent, reduced-occupancy; triggers PDL so the compute chain co-resides.
__global__ void scatter_ent(const int* __restrict__ tail, const int* __restrict__ st,
                            const int* __restrict__ org,  const float* __restrict__ entT,
                            float* __restrict__ out, int E) {
#if __CUDA_ARCH__ >= 900
    cudaTriggerProgrammaticLaunchCompletion();
#endif
    int l  = threadIdx.x & 31;
    int wid = (blockIdx.x * blockDim.x + threadIdx.x) >> 5;
    int nw  = (gridDim.x * blockDim.x) >> 5;
    for (int e0 = wid * 2; e0 < E; e0 += nw * 2) {
        int e1 = e0 + 1;
        int s0 = st[e0];
        int s1 = (e1 < E) ? st[e1] : 0;
        if (s0 == 1) {
            const float4* s = (const float4*)(entT + (size_t)org[e0] * D);
            float4* d = (float4*)(out + (size_t)tail[e0] * D);
            float4 v0 = __ldcs(s + l), v1 = __ldcs(s + l + 32);
            __stcs(d + l, v0); __stcs(d + l + 32, v1);
        }
        if (s1 == 1) {
            const float4* s = (const float4*)(entT + (size_t)org[e1] * D);
            float4* d = (float4*)(out + (size_t)tail[e1] * D);
            float4 v0 = __ldcs(s + l), v1 = __ldcs(s + l + 32);
            __stcs(d + l, v0); __stcs(d + l + 32, v1);
        }
    }
}

// ---------------- scatter B: state!=1 edges: out[tail] = obj_table[rel] ---------
__global__ void scatter_obj(const int* __restrict__ rel, const int* __restrict__ tail,
                            const int* __restrict__ st, float* __restrict__ out, int E) {
    int l  = threadIdx.x & 31;
    int wid = (blockIdx.x * blockDim.x + threadIdx.x) >> 5;
    int nw  = (gridDim.x * blockDim.x) >> 5;
    for (int e = wid; e < E; e += nw) {
        if (st[e] != 1) {
            const float4* s = (const float4*)(g_obj + (size_t)rel[e] * D);
            float4* d = (float4*)(out + (size_t)tail[e] * D);
            float4 v0 = __ldg(s + l), v1 = __ldg(s + l + 32);
            __stcs(d + l, v0); __stcs(d + l + 32, v1);
        }
    }
}

// --------------------------------- launcher -------------------------------------
extern "C" void kernel_launch(void* const* d_in, const int* in_sizes, int n_in,
                              void* d_out, int out_size) {
    const float* encoder = (const float*)d_in[0];
    const float* mask    = (const float*)d_in[1];
    const float* entT    = (const float*)d_in[2];
    const float* relT    = (const float*)d_in[3];
    const float* W_ih    = (const float*)d_in[4];
    const float* W_hh    = (const float*)d_in[5];
    const float* b_ih    = (const float*)d_in[6];
    const float* b_hh    = (const float*)d_in[7];
    const float* sub_W   = (const float*)d_in[8];
    const float* sub_b   = (const float*)d_in[9];
    const float* obj_W   = (const float*)d_in[10];
    const float* obj_b   = (const float*)d_in[11];
    const int*   rel_ids = (const int*)d_in[12];
    const int*   tail_ids= (const int*)d_in[13];
    const int*   state   = (const int*)d_in[14];
    const int*   origin  = (const int*)d_in[15];
    const int*   seed_p  = (const int*)d_in[16];
    float* out = (float*)d_out;

    int E = in_sizes[12];
    int R = in_sizes[3] / D;
    if (R > MAXR) R = MAXR;

    float *p_gh, *p_rj, *p_obj;
    cudaGetSymbolAddress((void**)&p_gh,  g_gh);
    cudaGetSymbolAddress((void**)&p_rj,  g_rj);
    cudaGetSymbolAddress((void**)&p_obj, g_obj);

    // 1) entity-gather scatter: independent of everything; reduced occupancy so
    //    the compute chain can co-reside via PDL.
    scatter_ent<<<740, 256>>>(tail_ids, state, origin, entT, out, E);

    // 2) k1 with ProgrammaticStreamSerialization: starts while scatter_ent runs.
    {
        cudaLaunchConfig_t cfg = {};
        cfg.gridDim = dim3(128); cfg.blockDim = dim3(256);
        cfg.dynamicSmemBytes = 0; cfg.stream = 0;
        cudaLaunchAttribute at[1];
        at[0].id = cudaLaunchAttributeProgrammaticStreamSerialization;
        at[0].val.programmaticStreamSerializationAllowed = 1;
        cfg.attrs = at; cfg.numAttrs = 1;
        cudaError_t err = cudaLaunchKernelEx(&cfg, k1_sub_gi0,
            sub_W, W_ih, mask, encoder, sub_b, b_ih, out, seed_p);
        if (err != cudaSuccess)
            k1_sub_gi0<<<128, 256>>>(sub_W, W_ih, mask, encoder, sub_b, b_ih, out, seed_p);
    }

    // 3) remaining chain (normal full-completion edges keep dependencies exact)
    k2_gh0<<<96, 256>>>(W_hh, b_hh);
    k3_gi<<<96, 256>>>(W_ih, b_ih);
    // gh_table = rel_table @ W_hh^T  (bias folded into rj_kernel)
    gemm_nt<128, 8, false><<<dim3((R + 63) / 64, G3 / 128), 256>>>(
        relT, W_hh, nullptr, p_gh, R, G3, D);
    rj_kernel<<<R, 256>>>(relT, b_hh, R);
    gemm_nt<64, 4, true><<<dim3((R + 63) / 64, D / 64), 256>>>(
        p_rj, obj_W, obj_b, p_obj, R, D, D);

    // 4) obj scatter (waits only on obj GEMM; disjoint rows vs scatter_ent)
    scatter_obj<<<1184, 256>>>(rel_ids, tail_ids, state, out, E);
}